// round 12
// baseline (speedup 1.0000x reference)
#include <cuda_runtime.h>
#include <math.h>

// Shapes fixed by the problem: B=64, S=512, D=128, K=1024
#define N_TOK 32768
#define DDIM  128
#define KCODE 1024
#define BM    64          // tokens per block (argmin kernel)
#define BN    128         // codes per tile
#define BMP   68          // padded token stride (272B rows: 16B-aligned, conflict-free)
#define BNP   132         // padded code stride (528B rows)
#define TPB   256
#define NBLK_B (N_TOK / 8)   // gather kernel blocks (8 warps/block, 1 token/warp)

// Scratch (no device allocation allowed -> __device__ globals)
__device__ int   g_idx[N_TOK];
__device__ int   g_counts[KCODE];
__device__ float g_bn[KCODE];     // ||e_k||^2 (full, fp32)
__device__ float g_A[N_TOK];      // ||z_n||^2 replicated with XLA-CPU reduce order
__device__ float g_part[NBLK_B];

__device__ __forceinline__ unsigned long long pack2(float a) {
    unsigned long long r;
    asm("mov.b64 %0, {%1, %1};" : "=l"(r) : "f"(a));
    return r;
}
__device__ __forceinline__ void ffma2(unsigned long long& d,
                                      unsigned long long a,
                                      unsigned long long b) {
    // packed dual fp32 FMA (Blackwell); each half is an IEEE fp32 FMA
    asm("fma.rn.f32x2 %0, %1, %2, %0;" : "+l"(d) : "l"(a), "l"(b));
}

// ---------------------------------------------------------------------------
// Kernel 0: B_k = ||e_k||^2 (order-insensitive: |err| ~1e-11 << dist ulp) and
// zero the counts (graph replays need the re-zero every launch).
// ---------------------------------------------------------------------------
__global__ void vq_prep(const float* __restrict__ emb) {
    int k = blockIdx.x * blockDim.x + threadIdx.x;
    if (k >= KCODE) return;
    const float4* e = reinterpret_cast<const float4*>(emb + (size_t)k * DDIM);
    float s = 0.f;
#pragma unroll 8
    for (int i = 0; i < DDIM / 4; ++i) {
        float4 v = e[i];
        s += v.x * v.x + v.y * v.y + v.z * v.z + v.w * v.w;
    }
    g_bn[k] = s;
    g_counts[k] = 0;
}

// ---------------------------------------------------------------------------
// Kernel 0b: A_n = ||z_n||^2 replicating XLA:CPU vectorized reduce on a
// 128-bit SIMD target: one 4-lane accumulator, lane j accumulates z[4i+j]
// with FMA (contracted square), finished by halving-shuffle tree
// (L0+L2)+(L1+L3). This must match the reference bitwise: dist rounds at
// ulp(128)=1.5e-5 and A errors of ~1e-5 reshuffle argmin grid-ties.
// ---------------------------------------------------------------------------
__global__ void vq_anorm(const float* __restrict__ z) {
    int n = blockIdx.x * blockDim.x + threadIdx.x;
    const float4* p = reinterpret_cast<const float4*>(z + (size_t)n * DDIM);
    float L0 = 0.f, L1 = 0.f, L2 = 0.f, L3 = 0.f;
#pragma unroll
    for (int i = 0; i < DDIM / 4; ++i) {
        float4 v = p[i];
        L0 = fmaf(v.x, v.x, L0);
        L1 = fmaf(v.y, v.y, L1);
        L2 = fmaf(v.z, v.z, L2);
        L3 = fmaf(v.w, v.w, L3);
    }
    float h0 = L0 + L2;          // halving shuffle: low half + high half
    float h1 = L1 + L3;
    g_A[n] = h0 + h1;
}

// ---------------------------------------------------------------------------
// Kernel 1: replicate r_k = fl(fl(A+B_k) - 2*dot_k) and argmin with
// lowest-index tie-break (== jnp.argmin over the fp32-gridded dist).
// dot_k is a single sequential ascending-d FMA chain per (token,code) —
// bit-identical to Eigen's gebp fp32 micro-kernel accumulation.
// Block: 64 tokens x 8 tiles of 128 codes. Thread frag: 4 tokens x 8 codes
// as 16 f32x2 packed accumulators.
// ---------------------------------------------------------------------------
__global__ __launch_bounds__(TPB)
void vq_argmin(const float* __restrict__ z, const float* __restrict__ emb) {
    extern __shared__ float smem[];
    float* zs  = smem;                    // [DDIM][BMP] transposed z tile
    float* es  = smem + DDIM * BMP;       // [DDIM][BNP] transposed e tile
    float* bnS = es + DDIM * BNP;         // [BN]

    const int tid = threadIdx.x;
    const int m0  = blockIdx.x * BM;

    // Stage z tile transposed: lanes span tokens -> STS conflict-free
#pragma unroll
    for (int it = 0; it < (BM * DDIM / 4) / TPB; ++it) {
        int idx = it * TPB + tid;
        int t = idx & (BM - 1);
        int q = idx >> 6;
        float4 v = reinterpret_cast<const float4*>(z + (size_t)(m0 + t) * DDIM)[q];
        int d0 = q * 4;
        zs[(d0 + 0) * BMP + t] = v.x;
        zs[(d0 + 1) * BMP + t] = v.y;
        zs[(d0 + 2) * BMP + t] = v.z;
        zs[(d0 + 3) * BMP + t] = v.w;
    }

    const int tx = tid & 15;   // code dim
    const int ty = tid >> 4;   // token dim
    const int tt = ty * 4;     // first local token
    const int cc = tx * 8;     // first local code in tile

    float Areg[4];
#pragma unroll
    for (int i = 0; i < 4; ++i) Areg[i] = g_A[m0 + tt + i];

    float best[4];
    int   bidx[4];
#pragma unroll
    for (int i = 0; i < 4; ++i) { best[i] = 3.4e38f; bidx[i] = 0; }

    for (int kt = 0; kt < KCODE / BN; ++kt) {
        const int n0 = kt * BN;
        __syncthreads();  // previous tile fully consumed (also covers zs on kt==0)

        // Stage e tile transposed (lanes span codes -> STS conflict-free)
#pragma unroll
        for (int it = 0; it < (BN * DDIM / 4) / TPB; ++it) {
            int idx = it * TPB + tid;
            int c = idx & (BN - 1);
            int q = idx >> 7;
            float4 v = reinterpret_cast<const float4*>(emb + (size_t)(n0 + c) * DDIM)[q];
            int d0 = q * 4;
            es[(d0 + 0) * BNP + c] = v.x;
            es[(d0 + 1) * BNP + c] = v.y;
            es[(d0 + 2) * BNP + c] = v.z;
            es[(d0 + 3) * BNP + c] = v.w;
        }
        if (tid < BN) bnS[tid] = g_bn[n0 + tid];
        __syncthreads();

        unsigned long long acc[4][4];
#pragma unroll
        for (int i = 0; i < 4; ++i)
#pragma unroll
            for (int j = 0; j < 4; ++j) acc[i][j] = 0ULL;  // (0.f,0.f)

        const float* zp = zs + tt;
        const float* ep = es + cc;
#pragma unroll 16
        for (int d = 0; d < DDIM; ++d) {   // strictly ascending d: Eigen order
            float4 zv = *reinterpret_cast<const float4*>(zp + d * BMP);
            ulonglong2 e01 = *reinterpret_cast<const ulonglong2*>(ep + d * BNP);
            ulonglong2 e23 = *reinterpret_cast<const ulonglong2*>(ep + d * BNP + 4);
            unsigned long long z0 = pack2(zv.x), z1 = pack2(zv.y);
            unsigned long long z2 = pack2(zv.z), z3 = pack2(zv.w);
            ffma2(acc[0][0], z0, e01.x); ffma2(acc[0][1], z0, e01.y);
            ffma2(acc[0][2], z0, e23.x); ffma2(acc[0][3], z0, e23.y);
            ffma2(acc[1][0], z1, e01.x); ffma2(acc[1][1], z1, e01.y);
            ffma2(acc[1][2], z1, e23.x); ffma2(acc[1][3], z1, e23.y);
            ffma2(acc[2][0], z2, e01.x); ffma2(acc[2][1], z2, e01.y);
            ffma2(acc[2][2], z2, e23.x); ffma2(acc[2][3], z2, e23.y);
            ffma2(acc[3][0], z3, e01.x); ffma2(acc[3][1], z3, e01.y);
            ffma2(acc[3][2], z3, e23.x); ffma2(acc[3][3], z3, e23.y);
        }

        // r = fl(fl(A+B) - 2*dot); running min, ascending code order + strict
        // '<' keeps the lowest index on grid ties (matches jnp.argmin).
#pragma unroll
        for (int j = 0; j < 4; ++j) {
            float b0 = bnS[cc + 2 * j];
            float b1 = bnS[cc + 2 * j + 1];
            int cb = n0 + cc + 2 * j;
#pragma unroll
            for (int i = 0; i < 4; ++i) {
                float lo = __uint_as_float((unsigned)(acc[i][j] & 0xffffffffULL));
                float hi = __uint_as_float((unsigned)(acc[i][j] >> 32));
                float u0 = Areg[i] + b0;      // first rounding (grid at ~128)
                float u1 = Areg[i] + b1;
                float r0 = u0 - 2.0f * lo;    // second rounding (2*lo exact)
                float r1 = u1 - 2.0f * hi;
                if (r0 < best[i]) { best[i] = r0; bidx[i] = cb; }
                if (r1 < best[i]) { best[i] = r1; bidx[i] = cb + 1; }
            }
        }
    }

    // Reduce over the 16 code-column lanes (lane = (ty&1)*16 + tx; xor<=8 stays in group)
#pragma unroll
    for (int off = 8; off >= 1; off >>= 1) {
#pragma unroll
        for (int i = 0; i < 4; ++i) {
            float os = __shfl_xor_sync(0xffffffffu, best[i], off);
            int   oi = __shfl_xor_sync(0xffffffffu, bidx[i], off);
            if (os < best[i] || (os == best[i] && oi < bidx[i])) {
                best[i] = os; bidx[i] = oi;
            }
        }
    }
    if (tx == 0) {
#pragma unroll
        for (int i = 0; i < 4; ++i) g_idx[m0 + tt + i] = bidx[i];
    }
}

// ---------------------------------------------------------------------------
// Kernel 2: straight-through output q = fl(z + fl(z_q - z)), per-block SSE
// partials (deterministic), integer count scatter for perplexity.
// ---------------------------------------------------------------------------
__global__ __launch_bounds__(TPB)
void vq_gather(const float* __restrict__ z, const float* __restrict__ emb,
               const unsigned char* __restrict__ mask, float* __restrict__ out) {
    __shared__ float ws[TPB / 32];
    int lane = threadIdx.x & 31;
    int w    = threadIdx.x >> 5;
    int n    = blockIdx.x * (TPB / 32) + w;

    int idx = g_idx[n];
    float4 e  = reinterpret_cast<const float4*>(emb + (size_t)idx * DDIM)[lane];
    float4 zv = reinterpret_cast<const float4*>(z + (size_t)n * DDIM)[lane];

    float dx = e.x - zv.x, dy = e.y - zv.y, dz = e.z - zv.z, dw = e.w - zv.w;
    float4 q;                              // zf + (z_q - zf): two roundings, like ref
    q.x = zv.x + dx; q.y = zv.y + dy; q.z = zv.z + dz; q.w = zv.w + dw;
    reinterpret_cast<float4*>(out)[(size_t)n * (DDIM / 4) + lane] = q;

    float s = dx * dx + dy * dy + dz * dz + dw * dw;
#pragma unroll
    for (int off = 16; off >= 1; off >>= 1) s += __shfl_xor_sync(0xffffffffu, s, off);

    if (lane == 0) {
        ws[w] = s;
        if (mask[n] == 0) atomicAdd(&g_counts[idx], 1);  // int atomic: deterministic
    }
    __syncthreads();
    if (threadIdx.x == 0) {
        float t = 0.f;
#pragma unroll
        for (int i = 0; i < TPB / 32; ++i) t += ws[i];
        g_part[blockIdx.x] = t;
    }
}

// ---------------------------------------------------------------------------
// Kernel 3: final scalars. loss = 1.25 * mean((z_q - z)^2); perplexity from counts.
// ---------------------------------------------------------------------------
__global__ void vq_final(float* __restrict__ out, int out_size) {
    __shared__ float red[1024];
    __shared__ float sseTot, totV;
    int t = threadIdx.x;

    float s = g_part[t] + g_part[t + 1024] + g_part[t + 2048] + g_part[t + 3072];
    red[t] = s; __syncthreads();
    for (int st = 512; st > 0; st >>= 1) { if (t < st) red[t] += red[t + st]; __syncthreads(); }
    if (t == 0) sseTot = red[0];
    __syncthreads();

    int c = g_counts[t];
    red[t] = (float)c; __syncthreads();
    for (int st = 512; st > 0; st >>= 1) { if (t < st) red[t] += red[t + st]; __syncthreads(); }
    if (t == 0) totV = red[0];
    __syncthreads();

    float p = (float)c / totV;
    red[t] = p * logf(p + 1e-10f);
    __syncthreads();
    for (int st = 512; st > 0; st >>= 1) { if (t < st) red[t] += red[t + st]; __syncthreads(); }

    if (t == 0) {
        float mse = sseTot / (float)(N_TOK * DDIM);
        out[out_size - 2] = mse + 0.25f * mse;   // q_latent + 0.25 * e_latent
        out[out_size - 1] = expf(-red[0]);       // perplexity
    }
}

// ---------------------------------------------------------------------------
extern "C" void kernel_launch(void* const* d_in, const int* in_sizes, int n_in,
                              void* d_out, int out_size) {
    const float*         z    = (const float*)d_in[0];
    const float*         emb  = (const float*)d_in[1];
    const unsigned char* mask = (const unsigned char*)d_in[2];
    float* out = (float*)d_out;

    const int smemBytes = (DDIM * BMP + DDIM * BNP + BN) * (int)sizeof(float); // 102912
    cudaFuncSetAttribute((const void*)vq_argmin,
                         cudaFuncAttributeMaxDynamicSharedMemorySize, smemBytes);

    vq_prep  <<<KCODE / 128, 128>>>(emb);
    vq_anorm <<<N_TOK / 256, 256>>>(z);
    vq_argmin<<<N_TOK / BM, TPB, smemBytes>>>(z, emb);
    vq_gather<<<N_TOK / (TPB / 32), TPB>>>(z, emb, mask, out);
    vq_final <<<1, 1024>>>(out, out_size);
}

// round 13
// speedup vs baseline: 1.0019x; 1.0019x over previous
#include <cuda_runtime.h>
#include <math.h>

// Shapes fixed by the problem: B=64, S=512, D=128, K=1024
#define N_TOK 32768
#define DDIM  128
#define KCODE 1024
#define BM    64          // tokens per block (argmin kernel)
#define BN    128         // codes per tile
#define BMP   68          // padded token stride (272B rows: 16B-aligned, conflict-free)
#define BNP   132         // padded code stride (528B rows)
#define TPB   256
#define NBLK_B (N_TOK / 8)   // gather kernel blocks (8 warps/block, 1 token/warp)

// Scratch (no device allocation allowed -> __device__ globals)
__device__ int   g_idx[N_TOK];
__device__ int   g_counts[KCODE];
__device__ float g_bn[KCODE];     // ||e_k||^2 (full, fp32)
__device__ float g_A[N_TOK];      // ||z_n||^2 replicated with XLA-CPU reduce order
__device__ float g_part[NBLK_B];

__device__ __forceinline__ unsigned long long pack2(float a) {
    unsigned long long r;
    asm("mov.b64 %0, {%1, %1};" : "=l"(r) : "f"(a));
    return r;
}
__device__ __forceinline__ void ffma2(unsigned long long& d,
                                      unsigned long long a,
                                      unsigned long long b) {
    // packed dual fp32 FMA (Blackwell); each half is an IEEE fp32 FMA
    asm("fma.rn.f32x2 %0, %1, %2, %0;" : "+l"(d) : "l"(a), "l"(b));
}

// ---------------------------------------------------------------------------
// Kernel 0: B_k = ||e_k||^2 (order-insensitive: |err| ~1e-11 << dist ulp) and
// zero the counts (graph replays need the re-zero every launch).
// ---------------------------------------------------------------------------
__global__ void vq_prep(const float* __restrict__ emb) {
    int k = blockIdx.x * blockDim.x + threadIdx.x;
    if (k >= KCODE) return;
    const float4* e = reinterpret_cast<const float4*>(emb + (size_t)k * DDIM);
    float s = 0.f;
#pragma unroll 8
    for (int i = 0; i < DDIM / 4; ++i) {
        float4 v = e[i];
        s += v.x * v.x + v.y * v.y + v.z * v.z + v.w * v.w;
    }
    g_bn[k] = s;
    g_counts[k] = 0;
}

// ---------------------------------------------------------------------------
// Kernel 0b: A_n = ||z_n||^2 replicating XLA:CPU vectorized reduce on a
// 128-bit SIMD target: one 4-lane accumulator, lane j accumulates z[4i+j]
// with FMA (contracted square), finished by halving-shuffle tree
// (L0+L2)+(L1+L3). This must match the reference bitwise: dist rounds at
// ulp(128)=1.5e-5 and A errors of ~1e-5 reshuffle argmin grid-ties.
// ---------------------------------------------------------------------------
__global__ void vq_anorm(const float* __restrict__ z) {
    int n = blockIdx.x * blockDim.x + threadIdx.x;
    const float4* p = reinterpret_cast<const float4*>(z + (size_t)n * DDIM);
    float L0 = 0.f, L1 = 0.f, L2 = 0.f, L3 = 0.f;
#pragma unroll
    for (int i = 0; i < DDIM / 4; ++i) {
        float4 v = p[i];
        L0 = fmaf(v.x, v.x, L0);
        L1 = fmaf(v.y, v.y, L1);
        L2 = fmaf(v.z, v.z, L2);
        L3 = fmaf(v.w, v.w, L3);
    }
    float h0 = L0 + L2;          // halving shuffle: low half + high half
    float h1 = L1 + L3;
    g_A[n] = h0 + h1;
}

// ---------------------------------------------------------------------------
// Kernel 1: replicate r_k = fl(fl(A+B_k) - 2*dot_k) and argmin with
// lowest-index tie-break (== jnp.argmin over the fp32-gridded dist).
// dot_k is a single sequential ascending-d FMA chain per (token,code) —
// bit-identical to Eigen's gebp fp32 micro-kernel accumulation.
// Block: 64 tokens x 8 tiles of 128 codes. Thread frag: 4 tokens x 8 codes
// as 16 f32x2 packed accumulators.
// ---------------------------------------------------------------------------
__global__ __launch_bounds__(TPB)
void vq_argmin(const float* __restrict__ z, const float* __restrict__ emb) {
    extern __shared__ float smem[];
    float* zs  = smem;                    // [DDIM][BMP] transposed z tile
    float* es  = smem + DDIM * BMP;       // [DDIM][BNP] transposed e tile
    float* bnS = es + DDIM * BNP;         // [BN]

    const int tid = threadIdx.x;
    const int m0  = blockIdx.x * BM;

    // Stage z tile transposed: lanes span tokens -> STS conflict-free
#pragma unroll
    for (int it = 0; it < (BM * DDIM / 4) / TPB; ++it) {
        int idx = it * TPB + tid;
        int t = idx & (BM - 1);
        int q = idx >> 6;
        float4 v = reinterpret_cast<const float4*>(z + (size_t)(m0 + t) * DDIM)[q];
        int d0 = q * 4;
        zs[(d0 + 0) * BMP + t] = v.x;
        zs[(d0 + 1) * BMP + t] = v.y;
        zs[(d0 + 2) * BMP + t] = v.z;
        zs[(d0 + 3) * BMP + t] = v.w;
    }

    const int tx = tid & 15;   // code dim
    const int ty = tid >> 4;   // token dim
    const int tt = ty * 4;     // first local token
    const int cc = tx * 8;     // first local code in tile

    float Areg[4];
#pragma unroll
    for (int i = 0; i < 4; ++i) Areg[i] = g_A[m0 + tt + i];

    float best[4];
    int   bidx[4];
#pragma unroll
    for (int i = 0; i < 4; ++i) { best[i] = 3.4e38f; bidx[i] = 0; }

    for (int kt = 0; kt < KCODE / BN; ++kt) {
        const int n0 = kt * BN;
        __syncthreads();  // previous tile fully consumed (also covers zs on kt==0)

        // Stage e tile transposed (lanes span codes -> STS conflict-free)
#pragma unroll
        for (int it = 0; it < (BN * DDIM / 4) / TPB; ++it) {
            int idx = it * TPB + tid;
            int c = idx & (BN - 1);
            int q = idx >> 7;
            float4 v = reinterpret_cast<const float4*>(emb + (size_t)(n0 + c) * DDIM)[q];
            int d0 = q * 4;
            es[(d0 + 0) * BNP + c] = v.x;
            es[(d0 + 1) * BNP + c] = v.y;
            es[(d0 + 2) * BNP + c] = v.z;
            es[(d0 + 3) * BNP + c] = v.w;
        }
        if (tid < BN) bnS[tid] = g_bn[n0 + tid];
        __syncthreads();

        unsigned long long acc[4][4];
#pragma unroll
        for (int i = 0; i < 4; ++i)
#pragma unroll
            for (int j = 0; j < 4; ++j) acc[i][j] = 0ULL;  // (0.f,0.f)

        const float* zp = zs + tt;
        const float* ep = es + cc;
#pragma unroll 16
        for (int d = 0; d < DDIM; ++d) {   // strictly ascending d: Eigen order
            float4 zv = *reinterpret_cast<const float4*>(zp + d * BMP);
            ulonglong2 e01 = *reinterpret_cast<const ulonglong2*>(ep + d * BNP);
            ulonglong2 e23 = *reinterpret_cast<const ulonglong2*>(ep + d * BNP + 4);
            unsigned long long z0 = pack2(zv.x), z1 = pack2(zv.y);
            unsigned long long z2 = pack2(zv.z), z3 = pack2(zv.w);
            ffma2(acc[0][0], z0, e01.x); ffma2(acc[0][1], z0, e01.y);
            ffma2(acc[0][2], z0, e23.x); ffma2(acc[0][3], z0, e23.y);
            ffma2(acc[1][0], z1, e01.x); ffma2(acc[1][1], z1, e01.y);
            ffma2(acc[1][2], z1, e23.x); ffma2(acc[1][3], z1, e23.y);
            ffma2(acc[2][0], z2, e01.x); ffma2(acc[2][1], z2, e01.y);
            ffma2(acc[2][2], z2, e23.x); ffma2(acc[2][3], z2, e23.y);
            ffma2(acc[3][0], z3, e01.x); ffma2(acc[3][1], z3, e01.y);
            ffma2(acc[3][2], z3, e23.x); ffma2(acc[3][3], z3, e23.y);
        }

        // r = fl(fl(A+B) - 2*dot); running min, ascending code order + strict
        // '<' keeps the lowest index on grid ties (matches jnp.argmin).
#pragma unroll
        for (int j = 0; j < 4; ++j) {
            float b0 = bnS[cc + 2 * j];
            float b1 = bnS[cc + 2 * j + 1];
            int cb = n0 + cc + 2 * j;
#pragma unroll
            for (int i = 0; i < 4; ++i) {
                float lo = __uint_as_float((unsigned)(acc[i][j] & 0xffffffffULL));
                float hi = __uint_as_float((unsigned)(acc[i][j] >> 32));
                float u0 = Areg[i] + b0;      // first rounding (grid at ~128)
                float u1 = Areg[i] + b1;
                float r0 = u0 - 2.0f * lo;    // second rounding (2*lo exact)
                float r1 = u1 - 2.0f * hi;
                if (r0 < best[i]) { best[i] = r0; bidx[i] = cb; }
                if (r1 < best[i]) { best[i] = r1; bidx[i] = cb + 1; }
            }
        }
    }

    // Reduce over the 16 code-column lanes (lane = (ty&1)*16 + tx; xor<=8 stays in group)
#pragma unroll
    for (int off = 8; off >= 1; off >>= 1) {
#pragma unroll
        for (int i = 0; i < 4; ++i) {
            float os = __shfl_xor_sync(0xffffffffu, best[i], off);
            int   oi = __shfl_xor_sync(0xffffffffu, bidx[i], off);
            if (os < best[i] || (os == best[i] && oi < bidx[i])) {
                best[i] = os; bidx[i] = oi;
            }
        }
    }
    if (tx == 0) {
#pragma unroll
        for (int i = 0; i < 4; ++i) g_idx[m0 + tt + i] = bidx[i];
    }
}

// ---------------------------------------------------------------------------
// Kernel 2: straight-through output q = fl(z + fl(z_q - z)), per-block SSE
// partials (deterministic), integer count scatter for perplexity.
// ---------------------------------------------------------------------------
__global__ __launch_bounds__(TPB)
void vq_gather(const float* __restrict__ z, const float* __restrict__ emb,
               const unsigned char* __restrict__ mask, float* __restrict__ out) {
    __shared__ float ws[TPB / 32];
    int lane = threadIdx.x & 31;
    int w    = threadIdx.x >> 5;
    int n    = blockIdx.x * (TPB / 32) + w;

    int idx = g_idx[n];
    float4 e  = reinterpret_cast<const float4*>(emb + (size_t)idx * DDIM)[lane];
    float4 zv = reinterpret_cast<const float4*>(z + (size_t)n * DDIM)[lane];

    float dx = e.x - zv.x, dy = e.y - zv.y, dz = e.z - zv.z, dw = e.w - zv.w;
    float4 q;                              // zf + (z_q - zf): two roundings, like ref
    q.x = zv.x + dx; q.y = zv.y + dy; q.z = zv.z + dz; q.w = zv.w + dw;
    reinterpret_cast<float4*>(out)[(size_t)n * (DDIM / 4) + lane] = q;

    float s = dx * dx + dy * dy + dz * dz + dw * dw;
#pragma unroll
    for (int off = 16; off >= 1; off >>= 1) s += __shfl_xor_sync(0xffffffffu, s, off);

    if (lane == 0) {
        ws[w] = s;
        if (mask[n] == 0) atomicAdd(&g_counts[idx], 1);  // int atomic: deterministic
    }
    __syncthreads();
    if (threadIdx.x == 0) {
        float t = 0.f;
#pragma unroll
        for (int i = 0; i < TPB / 32; ++i) t += ws[i];
        g_part[blockIdx.x] = t;
    }
}

// ---------------------------------------------------------------------------
// Kernel 3: final scalars. loss = 1.25 * mean((z_q - z)^2); perplexity from counts.
// ---------------------------------------------------------------------------
__global__ void vq_final(float* __restrict__ out, int out_size) {
    __shared__ float red[1024];
    __shared__ float sseTot, totV;
    int t = threadIdx.x;

    float s = g_part[t] + g_part[t + 1024] + g_part[t + 2048] + g_part[t + 3072];
    red[t] = s; __syncthreads();
    for (int st = 512; st > 0; st >>= 1) { if (t < st) red[t] += red[t + st]; __syncthreads(); }
    if (t == 0) sseTot = red[0];
    __syncthreads();

    int c = g_counts[t];
    red[t] = (float)c; __syncthreads();
    for (int st = 512; st > 0; st >>= 1) { if (t < st) red[t] += red[t + st]; __syncthreads(); }
    if (t == 0) totV = red[0];
    __syncthreads();

    float p = (float)c / totV;
    red[t] = p * logf(p + 1e-10f);
    __syncthreads();
    for (int st = 512; st > 0; st >>= 1) { if (t < st) red[t] += red[t + st]; __syncthreads(); }

    if (t == 0) {
        float mse = sseTot / (float)(N_TOK * DDIM);
        out[out_size - 2] = mse + 0.25f * mse;   // q_latent + 0.25 * e_latent
        out[out_size - 1] = expf(-red[0]);       // perplexity
    }
}

// ---------------------------------------------------------------------------
extern "C" void kernel_launch(void* const* d_in, const int* in_sizes, int n_in,
                              void* d_out, int out_size) {
    const float*         z    = (const float*)d_in[0];
    const float*         emb  = (const float*)d_in[1];
    const unsigned char* mask = (const unsigned char*)d_in[2];
    float* out = (float*)d_out;

    const int smemBytes = (DDIM * BMP + DDIM * BNP + BN) * (int)sizeof(float); // 102912
    cudaFuncSetAttribute((const void*)vq_argmin,
                         cudaFuncAttributeMaxDynamicSharedMemorySize, smemBytes);

    vq_prep  <<<KCODE / 128, 128>>>(emb);
    vq_anorm <<<N_TOK / 256, 256>>>(z);
    vq_argmin<<<N_TOK / BM, TPB, smemBytes>>>(z, emb);
    vq_gather<<<N_TOK / (TPB / 32), TPB>>>(z, emb, mask, out);
    vq_final <<<1, 1024>>>(out, out_size);
}